// round 1
// baseline (speedup 1.0000x reference)
#include <cuda_runtime.h>

#define TLEN 2048
#define BATCH 8192

__device__ __forceinline__ float frcp_fast(float x) {
    float r;
    asm("rcp.approx.f32 %0, %1;" : "=f"(r) : "f"(x));
    return r;
}

__global__ void __launch_bounds__(32, 8)
ekf_kernel(const float* __restrict__ price,
           const float* __restrict__ hurst,
           const float* __restrict__ sigv,
           float* __restrict__ out)
{
    const int b = blockIdx.x * blockDim.x + threadIdx.x;
    if (b >= BATCH) return;

    const float4* __restrict__ p4 = (const float4*)(price + (size_t)b * TLEN);
    const float4* __restrict__ h4 = (const float4*)(hurst + (size_t)b * TLEN);
    const float4* __restrict__ s4 = (const float4*)(sigv  + (size_t)b * TLEN);
    float4* __restrict__ o4 = (float4*)(out + (size_t)b * TLEN * 2);

    // first tile
    float4 pv = p4[0];
    float4 hv = h4[0];
    float4 sv = s4[0];

    // initial state: x = [z0, (z1 - z0)/dt], dt = 1; P = I
    float x0 = pv.x;
    float x1 = pv.y - pv.x;
    float p00 = 1.0f, p01 = 0.0f, p11 = 1.0f;

    const int NT = TLEN / 4;
    #pragma unroll 1
    for (int tb = 0; tb < NT; tb++) {
        // prefetch next tile (clamped index; uniform, no divergence)
        const int nidx = (tb + 1 < NT) ? (tb + 1) : (NT - 1);
        float4 pn = p4[nidx];
        float4 hn = h4[nidx];
        float4 sn = s4[nidx];

        const float zz[4] = {pv.x, pv.y, pv.z, pv.w};
        const float hh[4] = {hv.x, hv.y, hv.z, hv.w};
        const float ss[4] = {sv.x, sv.y, sv.z, sv.w};

        float ox[8];

        #pragma unroll
        for (int j = 0; j < 4; j++) {
            const float z  = zz[j];
            const float h  = hh[j];
            const float sg = ss[j];

            // rho = 0.5 + 0.5*sigmoid(10*(h-0.5)); a = dt*rho (dt=1)
            // sigmoid(u) = 1/(1+exp(-u)), exp via EX2 approx
            const float e = __expf(5.0f - 10.0f * h);
            const float a = fmaf(0.5f, frcp_fast(1.0f + e), 0.5f);

            // scale = max(100*sig, 1); q = 0.1*scale
            const float scale = fmaxf(100.0f * sg, 1.0f);
            const float q = 0.1f * scale;
            const float qs = q + scale;     // off the carried chain

            // --- predict P (symmetric: p00, p01, p11) ---
            const float p01n = fmaf(a, p11, p01);
            const float tmp  = p01n + p01;
            // S = p00_pred + scale = p00 + a*tmp + q + scale
            const float S    = fmaf(a, tmp, p00 + qs);
            const float p00n = S - scale;             // parallel with rcp
            const float p11n = p11 + q;

            const float Sinv = frcp_fast(S);          // 1e-6 term negligible (S >= 1)
            const float K0 = p00n * Sinv;
            const float K1 = p01n * Sinv;

            // --- predict/update x ---
            const float xp0 = fmaf(a, x1, x0);
            const float y   = z - xp0;
            x0 = fmaf(K0, y, xp0);
            x1 = fmaf(K1, y, x1);

            // --- update P ---
            p00 = fmaf(-K0, p00n, p00n);
            p01 = fmaf(-K0, p01n, p01n);
            p11 = fmaf(-K1, p01n, p11n);

            ox[2 * j + 0] = x0;
            ox[2 * j + 1] = x1;
        }

        float4 oA, oB;
        oA.x = ox[0]; oA.y = ox[1]; oA.z = ox[2]; oA.w = ox[3];
        oB.x = ox[4]; oB.y = ox[5]; oB.z = ox[6]; oB.w = ox[7];
        o4[2 * tb + 0] = oA;
        o4[2 * tb + 1] = oB;

        pv = pn; hv = hn; sv = sn;
    }
}

extern "C" void kernel_launch(void* const* d_in, const int* in_sizes, int n_in,
                              void* d_out, int out_size)
{
    const float* price = (const float*)d_in[0];
    const float* hurst = (const float*)d_in[1];
    const float* sigv  = (const float*)d_in[2];
    float* out = (float*)d_out;

    // 8192 threads: 32-thread blocks x 256 blocks -> single wave across 148 SMs
    ekf_kernel<<<BATCH / 32, 32>>>(price, hurst, sigv, out);
}